// round 9
// baseline (speedup 1.0000x reference)
#include <cuda_runtime.h>
#include <cstdint>

#define BATCH 2048
#define VOCAB 50000
#define EMB   100
#define CTX   10
#define KPF   128          // K padded to 128 int8 (4 x k32 mma steps)
#define VP    50176        // 392 * 128
#define BM    128
#define BN    128
#define NSPLIT 56
#define TPC    7           // B tiles per CTA = 392/56
#define STRB   144         // smem row stride bytes (128B data + 16 pad)
#define ABYTES (BM * STRB) // 18432
#define BBYTES (BN * STRB) // 18432
#define SMEM_TOTAL (ABYTES + 2 * BBYTES)  // 55296
#define CONVW   (VP * KPF / 4)            // uint32 words to convert
#define CONVBLK ((CONVW + 1279) / 1280)

#define CLH 1.6f
#define CLU 5.5f
#define QH (127.0f / CLH)
#define QU (127.0f / CLU)
// acc * SCALE_HALF = score/2
#define SCALE_HALF (0.5f * (CLH / 127.0f) * (CLU / 127.0f))

// Scratch (device globals)
__device__ __align__(16) char    g_hq[BATCH * KPF];   // h, s8
__device__ __align__(16) char    g_uq[VP * KPF];      // emb_u, s8
__device__ float                 g_negsum[BATCH];     // sum of tanh(score/2)
__device__ float                 g_pos[BATCH];        // -log_sigmoid(pos score)

__device__ __forceinline__ uint32_t s2u(const void* p) {
    uint32_t a;
    asm("{ .reg .u64 t; cvta.to.shared.u64 t, %1; cvt.u32.u64 %0, t; }" : "=r"(a) : "l"(p));
    return a;
}
__device__ __forceinline__ float tanh_approx(float x) {
    float y;
    asm("tanh.approx.f32 %0, %1;" : "=f"(y) : "f"(x));
    return y;
}
__device__ __forceinline__ void cpa16(uint32_t dst, const void* src) {
    asm volatile("cp.async.cg.shared.global [%0], [%1], 16;" :: "r"(dst), "l"(src));
}
__device__ __forceinline__ void ldsm4(uint32_t& r0, uint32_t& r1, uint32_t& r2,
                                      uint32_t& r3, uint32_t addr) {
    asm volatile("ldmatrix.sync.aligned.m8n8.x4.shared.b16 {%0,%1,%2,%3}, [%4];"
                 : "=r"(r0), "=r"(r1), "=r"(r2), "=r"(r3) : "r"(addr));
}
__device__ __forceinline__ int q8(float f, float clamp, float scale) {
    return __float2int_rn(fminf(fmaxf(f, -clamp), clamp) * scale);
}

// ---------------------------------------------------------------------------
// K0 (fused prologue):
//   blocks [0, BATCH):        h[b] -> s8; pos[b] = -logsig(u_y . h); zero negsum
//   blocks [BATCH, +CONVBLK): emb_u -> s8, padded [VP][KPF]
// ---------------------------------------------------------------------------
__global__ void __launch_bounds__(128) k_prep(const int* __restrict__ x,
                                              const int* __restrict__ y,
                                              const float* __restrict__ emb_v,
                                              const float* __restrict__ emb_u) {
    int t = threadIdx.x;  // 128
    if (blockIdx.x < BATCH) {
        int b = blockIdx.x;
        __shared__ int   ctx[CTX];
        __shared__ int   yy;
        __shared__ float hv[128];
        __shared__ float red[128];
        if (t < CTX) ctx[t] = x[b * CTX + t];
        if (t == 0) { yy = y[b]; g_negsum[b] = 0.0f; }
        __syncthreads();
        float s = 0.0f;
        if (t < EMB) {
#pragma unroll
            for (int c = 0; c < CTX; c++) s += emb_v[(size_t)ctx[c] * EMB + t];
            s *= 0.1f;
        }
        hv[t] = (t < EMB) ? s : 0.0f;
        red[t] = (t < EMB) ? s * emb_u[(size_t)yy * EMB + t] : 0.0f;
        __syncthreads();
#pragma unroll
        for (int o = 64; o; o >>= 1) {
            if (t < o) red[t] += red[t + o];
            __syncthreads();
        }
        if (t == 0) {
            float d = red[0];
            float ls = (d >= 0.0f) ? -log1pf(expf(-d)) : d - log1pf(expf(d));
            g_pos[b] = -ls;
        }
        if (t < KPF / 4) {
            char4 o4;
            o4.x = (char)q8(hv[4 * t + 0], CLH, QH);
            o4.y = (char)q8(hv[4 * t + 1], CLH, QH);
            o4.z = (char)q8(hv[4 * t + 2], CLH, QH);
            o4.w = (char)q8(hv[4 * t + 3], CLH, QH);
            ((char4*)(g_hq + (size_t)b * KPF))[t] = o4;
        }
    } else {
        int cb = blockIdx.x - BATCH;
#pragma unroll
        for (int wi = 0; wi < 10; wi++) {
            int i = cb * 1280 + wi * 128 + t;
            if (i < CONVW) {
                int v = i >> 5, k4 = (i & 31) * 4;
                char4 o4 = {0, 0, 0, 0};
                if (v < VOCAB) {
                    const float* row = emb_u + (size_t)v * EMB;
                    if (k4 + 0 < EMB) o4.x = (char)q8(row[k4 + 0], CLU, QU);
                    if (k4 + 1 < EMB) o4.y = (char)q8(row[k4 + 1], CLU, QU);
                    if (k4 + 2 < EMB) o4.z = (char)q8(row[k4 + 2], CLU, QU);
                    if (k4 + 3 < EMB) o4.w = (char)q8(row[k4 + 3], CLU, QU);
                }
                ((char4*)g_uq)[i] = o4;
            }
        }
    }
}

// ---------------------------------------------------------------------------
// K1: s8 GEMM (scores quantized) fused with tanh-sum.
//     CTA: M=128 rows pinned; streams 7 B tiles via cp.async double buffer.
//     8 warps = 4(M) x 2(N); warp tile 32x64; ldmatrix.x4 fragment loads;
//     mma.sync m16n8k32 s8 -> s32, interleaved with I2F+FMUL+TANH per 16 cols.
// ---------------------------------------------------------------------------
__global__ void __launch_bounds__(256, 2) k_gemm() {
    extern __shared__ __align__(16) char smem[];
    uint32_t sbase = s2u(smem);
    int t = threadIdx.x, w = t >> 5, lane = t & 31;
    int g = lane >> 2, tig = lane & 3;
    int arow0 = (w >> 1) * 32;     // warp M slice
    int brow0 = (w & 1) * 64;      // warp N slice
    int mbase = blockIdx.y * BM;
    int tile0 = blockIdx.x * TPC;

    uint32_t aoff0 = sbase + (arow0 + (lane & 15)) * STRB + (lane >> 4) * 16;
    uint32_t boff0 = (brow0 + ((lane >> 4) << 3) + (lane & 7)) * STRB
                   + ((lane >> 3) & 1) * 16;

    // Load A tile (128 rows x 128B)
    const uint4* gA = (const uint4*)(g_hq + (size_t)mbase * KPF);
#pragma unroll
    for (int i = 0; i < 4; i++) {
        int idx = t + i * 256;
        int r = idx >> 3, c = idx & 7;
        *(uint4*)(smem + r * STRB + c * 16) = gA[idx];
    }
    // Prime B tile 0
    {
        const char* gB = g_uq + (size_t)tile0 * BN * KPF;
        uint32_t sb = sbase + ABYTES;
#pragma unroll
        for (int i = 0; i < 4; i++) {
            int idx = t + i * 256;
            int r = idx >> 3, c = idx & 7;
            cpa16(sb + r * STRB + c * 16, gB + idx * 16);
        }
        asm volatile("cp.async.commit_group;" ::: "memory");
    }

    float rs[4] = {0.0f, 0.0f, 0.0f, 0.0f};

    for (int j = 0; j < TPC; j++) {
        asm volatile("cp.async.wait_group 0;" ::: "memory");
        __syncthreads();
        if (j + 1 < TPC) {
            const char* gB = g_uq + (size_t)(tile0 + j + 1) * BN * KPF;
            uint32_t sb = sbase + ABYTES + ((j + 1) & 1) * BBYTES;
#pragma unroll
            for (int i = 0; i < 4; i++) {
                int idx = t + i * 256;
                int r = idx >> 3, c = idx & 7;
                cpa16(sb + r * STRB + c * 16, gB + idx * 16);
            }
            asm volatile("cp.async.commit_group;" ::: "memory");
        }

        uint32_t bbuf = sbase + ABYTES + (j & 1) * BBYTES + boff0;

        // All A fragments for this tile (fixed across jn groups)
        uint32_t a[2][4][4];
#pragma unroll
        for (int im = 0; im < 2; im++)
#pragma unroll
            for (int ks = 0; ks < 4; ks++)
                ldsm4(a[im][ks][0], a[im][ks][1], a[im][ks][2], a[im][ks][3],
                      aoff0 + im * 16 * STRB + ks * 32);

#pragma unroll
        for (int jn = 0; jn < 4; jn++) {
            uint32_t b[4][4];
#pragma unroll
            for (int ks = 0; ks < 4; ks++)
                ldsm4(b[ks][0], b[ks][1], b[ks][2], b[ks][3],
                      bbuf + jn * 16 * STRB + ks * 32);

            int acc[2][2][4];
#pragma unroll
            for (int im = 0; im < 2; im++)
#pragma unroll
                for (int i2 = 0; i2 < 2; i2++)
#pragma unroll
                    for (int q = 0; q < 4; q++) acc[im][i2][q] = 0;

#pragma unroll
            for (int ks = 0; ks < 4; ks++)
#pragma unroll
                for (int im = 0; im < 2; im++)
#pragma unroll
                    for (int i2 = 0; i2 < 2; i2++)
                        asm volatile(
                            "mma.sync.aligned.m16n8k32.row.col.s32.s8.s8.s32 "
                            "{%0,%1,%2,%3}, {%4,%5,%6,%7}, {%8,%9}, {%0,%1,%2,%3};"
                            : "+r"(acc[im][i2][0]), "+r"(acc[im][i2][1]),
                              "+r"(acc[im][i2][2]), "+r"(acc[im][i2][3])
                            : "r"(a[im][ks][0]), "r"(a[im][ks][1]),
                              "r"(a[im][ks][2]), "r"(a[im][ks][3]),
                              "r"(b[ks][2 * i2]), "r"(b[ks][2 * i2 + 1]));

            // tanh of this 16-column group (interleaves with next jn's MMAs)
#pragma unroll
            for (int im = 0; im < 2; im++)
#pragma unroll
                for (int i2 = 0; i2 < 2; i2++)
#pragma unroll
                    for (int q = 0; q < 4; q++)
                        rs[im * 2 + (q >> 1)] +=
                            tanh_approx((float)acc[im][i2][q] * SCALE_HALF);
        }
    }

    // Reduce 4 column-lanes per row, one atomic per row
#pragma unroll
    for (int i = 0; i < 4; i++) {
        rs[i] += __shfl_xor_sync(0xffffffff, rs[i], 1);
        rs[i] += __shfl_xor_sync(0xffffffff, rs[i], 2);
    }
    if (tig == 0) {
#pragma unroll
        for (int im = 0; im < 2; im++)
#pragma unroll
            for (int h = 0; h < 2; h++) {
                int row = mbase + arow0 + im * 16 + h * 8 + g;
                atomicAdd(&g_negsum[row], rs[im * 2 + h]);
            }
    }
}

// ---------------------------------------------------------------------------
// K2 (fused tail): perb = pos + log(0.5*VOCAB - 0.5*sum_tanh); mean -> out
// ---------------------------------------------------------------------------
__global__ void k_final(float* __restrict__ out) {
    __shared__ float s[256];
    int t = threadIdx.x;
    float v = 0.0f;
    for (int i = t; i < BATCH; i += 256)
        v += g_pos[i] + logf(0.5f * (float)VOCAB - 0.5f * g_negsum[i]);
    s[t] = v;
    __syncthreads();
    for (int o = 128; o; o >>= 1) {
        if (t < o) s[t] += s[t + o];
        __syncthreads();
    }
    if (t == 0) out[0] = s[0] / (float)BATCH;
}

// ---------------------------------------------------------------------------
extern "C" void kernel_launch(void* const* d_in, const int* in_sizes, int n_in,
                              void* d_out, int out_size) {
    const int*   x     = (const int*)d_in[0];
    const int*   y     = (const int*)d_in[1];
    const float* emb_v = (const float*)d_in[2];
    const float* emb_u = (const float*)d_in[3];

    cudaFuncSetAttribute(k_gemm, cudaFuncAttributeMaxDynamicSharedMemorySize, SMEM_TOTAL);

    k_prep<<<BATCH + CONVBLK, 128>>>(x, y, emb_v, emb_u);
    dim3 grid(NSPLIT, BATCH / BM);  // 56 x 16
    k_gemm<<<grid, 256, SMEM_TOTAL>>>();
    k_final<<<1, 256>>>((float*)d_out);
}

// round 10
// speedup vs baseline: 2.1318x; 2.1318x over previous
#include <cuda_runtime.h>
#include <cuda_fp8.h>
#include <cstdint>

#define BATCH 2048
#define VOCAB 50000
#define EMB   100
#define CTX   10
#define KPF   128          // K padded to 128 fp8 (4 x k32 mma steps)
#define VP    50176        // 392 * 128
#define NT    392          // number of B tiles
#define BM    128
#define BN    128
#define NSLICE 37          // N-slices -> 37*16 = 592 CTAs = exactly 2 waves @ 2/SM
#define STRB   144         // smem row stride bytes (128B data + 16 pad)
#define ABYTES (BM * STRB) // 18432
#define BBYTES (BN * STRB) // 18432
#define SMEM_TOTAL (ABYTES + 2 * BBYTES)  // 55296
#define CONVW   (VP * KPF / 4)            // uint32 words to convert
#define CONVBLK ((CONVW + 1279) / 1280)

// Scratch (device globals)
__device__ __align__(16) char    g_hq[BATCH * KPF];   // h, e4m3
__device__ __align__(16) char    g_uq[VP * KPF];      // emb_u * 0.5, e4m3
__device__ float                 g_negsum[BATCH];     // sum of tanh(score/2)
__device__ float                 g_pos[BATCH];        // -log_sigmoid(pos score)

__device__ __forceinline__ uint32_t s2u(const void* p) {
    uint32_t a;
    asm("{ .reg .u64 t; cvta.to.shared.u64 t, %1; cvt.u32.u64 %0, t; }" : "=r"(a) : "l"(p));
    return a;
}
__device__ __forceinline__ float tanh_approx(float x) {
    float y;
    asm("tanh.approx.f32 %0, %1;" : "=f"(y) : "f"(x));
    return y;
}
__device__ __forceinline__ void cpa16(uint32_t dst, const void* src) {
    asm volatile("cp.async.cg.shared.global [%0], [%1], 16;" :: "r"(dst), "l"(src));
}
__device__ __forceinline__ void ldsm4(uint32_t& r0, uint32_t& r1, uint32_t& r2,
                                      uint32_t& r3, uint32_t addr) {
    asm volatile("ldmatrix.sync.aligned.m8n8.x4.shared.b16 {%0,%1,%2,%3}, [%4];"
                 : "=r"(r0), "=r"(r1), "=r"(r2), "=r"(r3) : "r"(addr));
}
__device__ __forceinline__ uint16_t fp8x2(float a, float b) {
    uint16_t r;
    asm("cvt.rn.satfinite.e4m3x2.f32 %0, %1, %2;" : "=h"(r) : "f"(b), "f"(a));
    return r;
}

// ---------------------------------------------------------------------------
// K0 (fused prologue):
//   blocks [0, BATCH):        h[b] -> e4m3; pos[b] = -logsig(u_y . h); zero negsum
//   blocks [BATCH, +CONVBLK): emb_u * 0.5 -> e4m3, padded [VP][KPF]
// ---------------------------------------------------------------------------
__global__ void __launch_bounds__(128) k_prep(const int* __restrict__ x,
                                              const int* __restrict__ y,
                                              const float* __restrict__ emb_v,
                                              const float* __restrict__ emb_u) {
    int t = threadIdx.x;  // 128
    if (blockIdx.x < BATCH) {
        int b = blockIdx.x;
        __shared__ int   ctx[CTX];
        __shared__ int   yy;
        __shared__ float hv[128];
        __shared__ float red[128];
        if (t < CTX) ctx[t] = x[b * CTX + t];
        if (t == 0) { yy = y[b]; g_negsum[b] = 0.0f; }
        __syncthreads();
        float s = 0.0f;
        if (t < EMB) {
#pragma unroll
            for (int c = 0; c < CTX; c++) s += emb_v[(size_t)ctx[c] * EMB + t];
            s *= 0.1f;
        }
        hv[t] = (t < EMB) ? s : 0.0f;
        red[t] = (t < EMB) ? s * emb_u[(size_t)yy * EMB + t] : 0.0f;
        __syncthreads();
#pragma unroll
        for (int o = 64; o; o >>= 1) {
            if (t < o) red[t] += red[t + o];
            __syncthreads();
        }
        if (t == 0) {
            float d = red[0];
            float ls = (d >= 0.0f) ? -log1pf(expf(-d)) : d - log1pf(expf(d));
            g_pos[b] = -ls;
        }
        if (t < KPF / 2)
            ((uint16_t*)(g_hq + (size_t)b * KPF))[t] = fp8x2(hv[2 * t], hv[2 * t + 1]);
    } else {
        int cb = blockIdx.x - BATCH;
#pragma unroll
        for (int wi = 0; wi < 10; wi++) {
            int i = cb * 1280 + wi * 128 + t;
            if (i < CONVW) {
                int v = i >> 5, k4 = (i & 31) * 4;
                uint32_t out = 0;
                if (v < VOCAB) {
                    float f[4];
#pragma unroll
                    for (int q = 0; q < 4; q++) {
                        int k = k4 + q;
                        f[q] = (k < EMB) ? 0.5f * emb_u[(size_t)v * EMB + k] : 0.0f;
                    }
                    out = (uint32_t)fp8x2(f[0], f[1]) | ((uint32_t)fp8x2(f[2], f[3]) << 16);
                }
                ((uint32_t*)g_uq)[i] = out;
            }
        }
    }
}

// ---------------------------------------------------------------------------
// K1: fp8 GEMM (acc = (h @ U^T)/2 via pre-scaled U) fused with tanh-sum.
//     Grid 37x16 = 592 CTAs = exactly 2 waves at 2 CTAs/SM (no straggler wave).
//     Each CTA: A tile pinned, streams its 10-11 B tiles via cp.async
//     double buffer; MMA and TANH interleaved at 16-column granularity.
// ---------------------------------------------------------------------------
__global__ void __launch_bounds__(256, 2) k_gemm() {
    extern __shared__ __align__(16) char smem[];
    uint32_t sbase = s2u(smem);
    int t = threadIdx.x, w = t >> 5, lane = t & 31;
    int g = lane >> 2, tig = lane & 3;
    int arow0 = (w >> 1) * 32;     // warp M slice
    int brow0 = (w & 1) * 64;      // warp N slice
    int mbase = blockIdx.y * BM;
    int t0 = (blockIdx.x * NT) / NSLICE;
    int t1 = ((blockIdx.x + 1) * NT) / NSLICE;

    uint32_t aoff0 = sbase + (arow0 + (lane & 15)) * STRB + (lane >> 4) * 16;
    uint32_t boff0 = (brow0 + ((lane >> 4) << 3) + (lane & 7)) * STRB
                   + ((lane >> 3) & 1) * 16;

    // Load A tile (128 rows x 128B)
    const uint4* gA = (const uint4*)(g_hq + (size_t)mbase * KPF);
#pragma unroll
    for (int i = 0; i < 4; i++) {
        int idx = t + i * 256;
        int r = idx >> 3, c = idx & 7;
        *(uint4*)(smem + r * STRB + c * 16) = gA[idx];
    }
    // Prime B tile t0
    {
        const char* gB = g_uq + (size_t)t0 * BN * KPF;
        uint32_t sb = sbase + ABYTES;
#pragma unroll
        for (int i = 0; i < 4; i++) {
            int idx = t + i * 256;
            int r = idx >> 3, c = idx & 7;
            cpa16(sb + r * STRB + c * 16, gB + idx * 16);
        }
        asm volatile("cp.async.commit_group;" ::: "memory");
    }

    float rs[4] = {0.0f, 0.0f, 0.0f, 0.0f};

    for (int j = t0; j < t1; j++) {
        int par = (j - t0) & 1;
        asm volatile("cp.async.wait_group 0;" ::: "memory");
        __syncthreads();
        if (j + 1 < t1) {
            const char* gB = g_uq + (size_t)(j + 1) * BN * KPF;
            uint32_t sb = sbase + ABYTES + (par ^ 1) * BBYTES;
#pragma unroll
            for (int i = 0; i < 4; i++) {
                int idx = t + i * 256;
                int r = idx >> 3, c = idx & 7;
                cpa16(sb + r * STRB + c * 16, gB + idx * 16);
            }
            asm volatile("cp.async.commit_group;" ::: "memory");
        }

        uint32_t bbuf = sbase + ABYTES + par * BBYTES + boff0;

        // All A fragments for this tile (fixed across jn groups)
        uint32_t a[2][4][4];
#pragma unroll
        for (int im = 0; im < 2; im++)
#pragma unroll
            for (int ks = 0; ks < 4; ks++)
                ldsm4(a[im][ks][0], a[im][ks][1], a[im][ks][2], a[im][ks][3],
                      aoff0 + im * 16 * STRB + ks * 32);

#pragma unroll
        for (int jn = 0; jn < 4; jn++) {
            uint32_t b[4][4];
#pragma unroll
            for (int ks = 0; ks < 4; ks++)
                ldsm4(b[ks][0], b[ks][1], b[ks][2], b[ks][3],
                      bbuf + jn * 16 * STRB + ks * 32);

            float acc[2][2][4];
#pragma unroll
            for (int im = 0; im < 2; im++)
#pragma unroll
                for (int i2 = 0; i2 < 2; i2++)
#pragma unroll
                    for (int q = 0; q < 4; q++) acc[im][i2][q] = 0.0f;

#pragma unroll
            for (int ks = 0; ks < 4; ks++)
#pragma unroll
                for (int im = 0; im < 2; im++)
#pragma unroll
                    for (int i2 = 0; i2 < 2; i2++)
                        asm volatile(
                            "mma.sync.aligned.m16n8k32.row.col.f32.e4m3.e4m3.f32 "
                            "{%0,%1,%2,%3}, {%4,%5,%6,%7}, {%8,%9}, {%0,%1,%2,%3};"
                            : "+f"(acc[im][i2][0]), "+f"(acc[im][i2][1]),
                              "+f"(acc[im][i2][2]), "+f"(acc[im][i2][3])
                            : "r"(a[im][ks][0]), "r"(a[im][ks][1]),
                              "r"(a[im][ks][2]), "r"(a[im][ks][3]),
                              "r"(b[ks][2 * i2]), "r"(b[ks][2 * i2 + 1]));

            // tanh of this 16-column group (interleaves with next jn's MMAs)
#pragma unroll
            for (int im = 0; im < 2; im++)
#pragma unroll
                for (int i2 = 0; i2 < 2; i2++)
#pragma unroll
                    for (int q = 0; q < 4; q++)
                        rs[im * 2 + (q >> 1)] += tanh_approx(acc[im][i2][q]);
        }
    }

    // Reduce 4 column-lanes per row, one atomic per row
#pragma unroll
    for (int i = 0; i < 4; i++) {
        rs[i] += __shfl_xor_sync(0xffffffff, rs[i], 1);
        rs[i] += __shfl_xor_sync(0xffffffff, rs[i], 2);
    }
    if (tig == 0) {
#pragma unroll
        for (int im = 0; im < 2; im++)
#pragma unroll
            for (int h = 0; h < 2; h++) {
                int row = mbase + arow0 + im * 16 + h * 8 + g;
                atomicAdd(&g_negsum[row], rs[im * 2 + h]);
            }
    }
}

// ---------------------------------------------------------------------------
// K2 (fused tail): perb = pos + log(0.5*VOCAB - 0.5*sum_tanh); mean -> out
// ---------------------------------------------------------------------------
__global__ void k_final(float* __restrict__ out) {
    __shared__ float s[256];
    int t = threadIdx.x;
    float v = 0.0f;
    for (int i = t; i < BATCH; i += 256)
        v += g_pos[i] + logf(0.5f * (float)VOCAB - 0.5f * g_negsum[i]);
    s[t] = v;
    __syncthreads();
    for (int o = 128; o; o >>= 1) {
        if (t < o) s[t] += s[t + o];
        __syncthreads();
    }
    if (t == 0) out[0] = s[0] / (float)BATCH;
}

// ---------------------------------------------------------------------------
extern "C" void kernel_launch(void* const* d_in, const int* in_sizes, int n_in,
                              void* d_out, int out_size) {
    const int*   x     = (const int*)d_in[0];
    const int*   y     = (const int*)d_in[1];
    const float* emb_v = (const float*)d_in[2];
    const float* emb_u = (const float*)d_in[3];

    cudaFuncSetAttribute(k_gemm, cudaFuncAttributeMaxDynamicSharedMemorySize, SMEM_TOTAL);

    k_prep<<<BATCH + CONVBLK, 128>>>(x, y, emb_v, emb_u);
    dim3 grid(NSLICE, BATCH / BM);  // 37 x 16 = 592 CTAs
    k_gemm<<<grid, 256, SMEM_TOTAL>>>();
    k_final<<<1, 256>>>((float*)d_out);
}

// round 11
// speedup vs baseline: 2.2507x; 1.0558x over previous
#include <cuda_runtime.h>
#include <cuda_bf16.h>
#include <cstdint>

#define BATCH 2048
#define VOCAB 50000
#define EMB   100
#define CTX   10
#define KP    112          // K padded to 112 bf16 (7 x k16 mma steps)
#define VP    50176        // 784 * 64
#define NT    784          // number of 64-row B tiles
#define BM    128
#define BN    64
#define NSLICE 27          // 27*16 = 432 CTAs ~= one wave at 3 CTAs/SM
#define STRB   240         // smem row stride bytes (224B data + 16 pad)
#define ABYTES (BM * STRB) // 30720
#define BBYTES (BN * STRB) // 15360
#define SMEM_TOTAL (ABYTES + 2 * BBYTES)  // 61440
#define CONVW   (VP * 28)                 // 8B-units to convert (28 per row)
#define CONVBLK ((CONVW + 1279) / 1280)

// Scratch (device globals)
__device__ __align__(16) __nv_bfloat16  g_hb[BATCH * KP];   // h, bf16
__device__ __align__(16) __nv_bfloat16  g_ub[VP * KP];      // emb_u * 0.5, bf16
__device__ float                        g_negsum[BATCH];    // sum of tanh(score/2)
__device__ float                        g_pos[BATCH];       // -log_sigmoid(pos)

__device__ __forceinline__ uint32_t s2u(const void* p) {
    uint32_t a;
    asm("{ .reg .u64 t; cvta.to.shared.u64 t, %1; cvt.u32.u64 %0, t; }" : "=r"(a) : "l"(p));
    return a;
}
__device__ __forceinline__ float tanh_approx(float x) {
    float y;
    asm("tanh.approx.f32 %0, %1;" : "=f"(y) : "f"(x));
    return y;
}
__device__ __forceinline__ void cpa16(uint32_t dst, const void* src) {
    asm volatile("cp.async.cg.shared.global [%0], [%1], 16;" :: "r"(dst), "l"(src));
}
__device__ __forceinline__ void ldsm4(uint32_t& r0, uint32_t& r1, uint32_t& r2,
                                      uint32_t& r3, uint32_t addr) {
    asm volatile("ldmatrix.sync.aligned.m8n8.x4.shared.b16 {%0,%1,%2,%3}, [%4];"
                 : "=r"(r0), "=r"(r1), "=r"(r2), "=r"(r3) : "r"(addr));
}
// pack [lo, hi] as consecutive bf16 in memory order
__device__ __forceinline__ uint32_t bfpack(float lo, float hi) {
    uint32_t r;
    asm("cvt.rn.bf16x2.f32 %0, %1, %2;" : "=r"(r) : "f"(hi), "f"(lo));
    return r;
}

// ---------------------------------------------------------------------------
// K0 (fused prologue):
//   blocks [0, BATCH):        h[b] -> bf16; pos[b] = -logsig(u_y . h); zero negsum
//   blocks [BATCH, +CONVBLK): emb_u * 0.5 -> bf16, padded [VP][KP] (float4 loads)
// ---------------------------------------------------------------------------
__global__ void __launch_bounds__(128) k_prep(const int* __restrict__ x,
                                              const int* __restrict__ y,
                                              const float* __restrict__ emb_v,
                                              const float* __restrict__ emb_u) {
    int t = threadIdx.x;  // 128
    if (blockIdx.x < BATCH) {
        int b = blockIdx.x;
        __shared__ int   ctx[CTX];
        __shared__ int   yy;
        __shared__ float hv[KP];
        __shared__ float red[128];
        if (t < CTX) ctx[t] = x[b * CTX + t];
        if (t == 0) { yy = y[b]; g_negsum[b] = 0.0f; }
        __syncthreads();
        float s = 0.0f;
        if (t < EMB) {
#pragma unroll
            for (int c = 0; c < CTX; c++) s += emb_v[(size_t)ctx[c] * EMB + t];
            s *= 0.1f;
        }
        if (t < KP) hv[t] = (t < EMB) ? s : 0.0f;
        red[t] = (t < EMB) ? s * emb_u[(size_t)yy * EMB + t] : 0.0f;
        __syncthreads();
#pragma unroll
        for (int o = 64; o; o >>= 1) {
            if (t < o) red[t] += red[t + o];
            __syncthreads();
        }
        if (t == 0) {
            float d = red[0];
            float ls = (d >= 0.0f) ? -log1pf(expf(-d)) : d - log1pf(expf(d));
            g_pos[b] = -ls;
        }
        if (t < KP / 4) {
            uint2 o2;
            o2.x = bfpack(hv[4 * t], hv[4 * t + 1]);
            o2.y = bfpack(hv[4 * t + 2], hv[4 * t + 3]);
            ((uint2*)(g_hb + (size_t)b * KP))[t] = o2;
        }
    } else {
        int cb = blockIdx.x - BATCH;
#pragma unroll
        for (int wi = 0; wi < 10; wi++) {
            int i = cb * 1280 + wi * 128 + t;      // 8B-unit index
            if (i < CONVW) {
                int v = i / 28, k4 = (i % 28) * 4;
                uint2 o2 = {0u, 0u};
                if (v < VOCAB && k4 < EMB) {
                    // k4 multiple of 4, k4 <= 96 -> float4 fully in-bounds
                    float4 f = *(const float4*)(emb_u + (size_t)v * EMB + k4);
                    o2.x = bfpack(0.5f * f.x, 0.5f * f.y);
                    o2.y = bfpack(0.5f * f.z, 0.5f * f.w);
                }
                ((uint2*)g_ub)[(size_t)v * 28 + (k4 >> 2)] = o2;
            }
        }
    }
}

// ---------------------------------------------------------------------------
// K1: bf16 GEMM (acc = (h @ U^T)/2 via pre-scaled U) fused with tanh-sum.
//     BN=64 tiles -> 61.4KB smem/CTA -> 3 CTAs/SM (24 warps) for MMA-pipe
//     busyness. 8 warps = 4(M) x 2(N); warp tile 32x32; ldmatrix.x4;
//     mma.sync m16n8k16 bf16 -> f32; epilogue MUFU.TANH + FADD per score.
// ---------------------------------------------------------------------------
__global__ void __launch_bounds__(256, 3) k_gemm() {
    extern __shared__ __align__(16) char smem[];
    uint32_t sbase = s2u(smem);
    int t = threadIdx.x, w = t >> 5, lane = t & 31;
    int g = lane >> 2, tig = lane & 3;
    int arow0 = (w >> 1) * 32;     // warp M slice
    int brow0 = (w & 1) * 32;      // warp N slice
    int mbase = blockIdx.y * BM;
    int t0 = (blockIdx.x * NT) / NSLICE;
    int t1 = ((blockIdx.x + 1) * NT) / NSLICE;

    uint32_t aoff0 = sbase + (arow0 + (lane & 15)) * STRB + (lane >> 4) * 16;
    uint32_t boff0 = (brow0 + ((lane >> 4) << 3) + (lane & 7)) * STRB
                   + ((lane >> 3) & 1) * 16;

    // Load A tile (128 rows x 224B)
    const uint4* gA = (const uint4*)(g_hb + (size_t)mbase * KP);
#pragma unroll
    for (int i = 0; i < 7; i++) {
        int idx = t + i * 256;          // 1792 16B chunks
        int r = idx / 14, c = idx % 14;
        *(uint4*)(smem + r * STRB + c * 16) = gA[idx];
    }
    // Prime B tile t0 (64 rows x 14 chunks = 896)
    {
        const char* gB = (const char*)(g_ub + (size_t)t0 * BN * KP);
        uint32_t sb = sbase + ABYTES;
#pragma unroll
        for (int i = 0; i < 4; i++) {
            int idx = t + i * 256;
            if (idx < BN * 14) {
                int r = idx / 14, c = idx % 14;
                cpa16(sb + r * STRB + c * 16, gB + idx * 16);
            }
        }
        asm volatile("cp.async.commit_group;" ::: "memory");
    }

    float rs[4] = {0.0f, 0.0f, 0.0f, 0.0f};

    for (int j = t0; j < t1; j++) {
        int par = (j - t0) & 1;
        asm volatile("cp.async.wait_group 0;" ::: "memory");
        __syncthreads();
        if (j + 1 < t1) {
            const char* gB = (const char*)(g_ub + (size_t)(j + 1) * BN * KP);
            uint32_t sb = sbase + ABYTES + (par ^ 1) * BBYTES;
#pragma unroll
            for (int i = 0; i < 4; i++) {
                int idx = t + i * 256;
                if (idx < BN * 14) {
                    int r = idx / 14, c = idx % 14;
                    cpa16(sb + r * STRB + c * 16, gB + idx * 16);
                }
            }
            asm volatile("cp.async.commit_group;" ::: "memory");
        }

        uint32_t bbuf = sbase + ABYTES + par * BBYTES + boff0;

        float acc[2][2][2][4];   // [im][jn][i2][q] = 32 regs
#pragma unroll
        for (int im = 0; im < 2; im++)
#pragma unroll
            for (int jn = 0; jn < 2; jn++)
#pragma unroll
                for (int i2 = 0; i2 < 2; i2++)
#pragma unroll
                    for (int q = 0; q < 4; q++) acc[im][jn][i2][q] = 0.0f;

#pragma unroll
        for (int ks = 0; ks < 7; ks++) {
            int kb = ks * 32;               // byte offset (16 bf16)
            uint32_t a[2][4], b[2][4];
#pragma unroll
            for (int im = 0; im < 2; im++)
                ldsm4(a[im][0], a[im][1], a[im][2], a[im][3],
                      aoff0 + im * 16 * STRB + kb);
#pragma unroll
            for (int jn = 0; jn < 2; jn++)
                ldsm4(b[jn][0], b[jn][1], b[jn][2], b[jn][3],
                      bbuf + jn * 16 * STRB + kb);
#pragma unroll
            for (int im = 0; im < 2; im++)
#pragma unroll
                for (int jn = 0; jn < 2; jn++)
#pragma unroll
                    for (int i2 = 0; i2 < 2; i2++)
                        asm volatile(
                            "mma.sync.aligned.m16n8k16.row.col.f32.bf16.bf16.f32 "
                            "{%0,%1,%2,%3}, {%4,%5,%6,%7}, {%8,%9}, {%0,%1,%2,%3};"
                            : "+f"(acc[im][jn][i2][0]), "+f"(acc[im][jn][i2][1]),
                              "+f"(acc[im][jn][i2][2]), "+f"(acc[im][jn][i2][3])
                            : "r"(a[im][0]), "r"(a[im][1]),
                              "r"(a[im][2]), "r"(a[im][3]),
                              "r"(b[jn][2 * i2]), "r"(b[jn][2 * i2 + 1]));
        }

        // Epilogue: acc already = score/2; sum tanh only (pads give exact 0)
#pragma unroll
        for (int im = 0; im < 2; im++)
#pragma unroll
            for (int jn = 0; jn < 2; jn++)
#pragma unroll
                for (int i2 = 0; i2 < 2; i2++)
#pragma unroll
                    for (int q = 0; q < 4; q++)
                        rs[im * 2 + (q >> 1)] += tanh_approx(acc[im][jn][i2][q]);
    }

    // Reduce 4 column-lanes per row, one atomic per row
#pragma unroll
    for (int i = 0; i < 4; i++) {
        rs[i] += __shfl_xor_sync(0xffffffff, rs[i], 1);
        rs[i] += __shfl_xor_sync(0xffffffff, rs[i], 2);
    }
    if (tig == 0) {
#pragma unroll
        for (int im = 0; im < 2; im++)
#pragma unroll
            for (int h = 0; h < 2; h++) {
                int row = mbase + arow0 + im * 16 + h * 8 + g;
                atomicAdd(&g_negsum[row], rs[im * 2 + h]);
            }
    }
}

// ---------------------------------------------------------------------------
// K2 (fused tail): perb = pos + log(0.5*VOCAB - 0.5*sum_tanh); mean -> out
// ---------------------------------------------------------------------------
__global__ void k_final(float* __restrict__ out) {
    __shared__ float s[256];
    int t = threadIdx.x;
    float v = 0.0f;
    for (int i = t; i < BATCH; i += 256)
        v += g_pos[i] + logf(0.5f * (float)VOCAB - 0.5f * g_negsum[i]);
    s[t] = v;
    __syncthreads();
    for (int o = 128; o; o >>= 1) {
        if (t < o) s[t] += s[t + o];
        __syncthreads();
    }
    if (t == 0) out[0] = s[0] / (float)BATCH;
}

// ---------------------------------------------------------------------------
extern "C" void kernel_launch(void* const* d_in, const int* in_sizes, int n_in,
                              void* d_out, int out_size) {
    const int*   x     = (const int*)d_in[0];
    const int*   y     = (const int*)d_in[1];
    const float* emb_v = (const float*)d_in[2];
    const float* emb_u = (const float*)d_in[3];

    cudaFuncSetAttribute(k_gemm, cudaFuncAttributeMaxDynamicSharedMemorySize, SMEM_TOTAL);

    k_prep<<<BATCH + CONVBLK, 128>>>(x, y, emb_v, emb_u);
    dim3 grid(NSLICE, BATCH / BM);  // 27 x 16 = 432 CTAs
    k_gemm<<<grid, 256, SMEM_TOTAL>>>();
    k_final<<<1, 256>>>((float*)d_out);
}